// round 3
// baseline (speedup 1.0000x reference)
#include <cuda_runtime.h>

#define NB 4
#define NT 8192
#define NC 128
#define NL 40
#define TILE 64
#define NTHREADS 256

typedef unsigned long long u64;

__device__ __forceinline__ u64 pk2(float lo, float hi) {
    u64 r; asm("mov.b64 %0, {%1, %2};" : "=l"(r) : "f"(lo), "f"(hi)); return r;
}
__device__ __forceinline__ u64 bcast2(float v) {
    u64 r; asm("mov.b64 %0, {%1, %1};" : "=l"(r) : "f"(v)); return r;
}
__device__ __forceinline__ u64 ffma2(u64 a, u64 b, u64 c) {
    u64 d; asm("fma.rn.f32x2 %0, %1, %2, %3;" : "=l"(d) : "l"(a), "l"(b), "l"(c)); return d;
}
__device__ __forceinline__ void unpk2(u64 v, float& lo, float& hi) {
    asm("mov.b64 {%0, %1}, %2;" : "=f"(lo), "=f"(hi) : "l"(v));
}

// Persistent device scratch (allocation-free rule: __device__ globals)
__device__ float g_hA[NB * NT * NC];
__device__ float g_hB[NB * NT * NC];
__device__ float g_skip[NB * NT * NC];
__device__ float g_wconv[NL * 2 * NC * 2 * NC];  // [l][tap][c(128)][o(256)]
__device__ float g_wpost[NL * NC * NC];          // [l][c][o]
__device__ float g_lin[2][NC * NC];              // [which][i][o]

// ---------------- weight transposes (run every launch; deterministic) -------

__global__ void tconv_kernel(const float* __restrict__ w) {
    // w: [L][256][128][2] -> g_wconv [l][tap][c][o]
    int idx = blockIdx.x * blockDim.x + threadIdx.x;  // exact: NL*256*128*2
    int tap = idx & 1;
    int c = (idx >> 1) & 127;
    int o = (idx >> 8) & 255;
    int l = idx >> 16;
    g_wconv[((l * 2 + tap) * 128 + c) * 256 + o] = w[idx];
}

__global__ void tpost_kernel(const float* __restrict__ w) {
    // w: [L][128 o][128 c] -> [l][c][o]
    int idx = blockIdx.x * blockDim.x + threadIdx.x;  // exact: NL*128*128
    int c = idx & 127;
    int o = (idx >> 7) & 127;
    int l = idx >> 14;
    g_wpost[(l * 128 + c) * 128 + o] = w[idx];
}

__global__ void tlin_kernel(const float* __restrict__ w, int which) {
    // w: [128 o][128 i] -> [i][o]
    int idx = blockIdx.x * blockDim.x + threadIdx.x;  // exact: 128*128
    int i = idx & 127;
    int o = idx >> 7;
    g_lin[which][i * 128 + o] = w[idx];
}

// ---------------- pre-net: causal conv1d k=3, 1 -> 128 channels -------------

__global__ void pre_kernel(const float* __restrict__ x,
                           const float* __restrict__ w,
                           const float* __restrict__ b) {
    int bt = blockIdx.x;       // b*NT + t
    int bb = bt >> 13;         // / 8192
    int t = bt & 8191;
    int c = threadIdx.x;
    const float* xb = x + bb * NT;
    float x0 = (t >= 2) ? xb[t - 2] : 0.f;
    float x1 = (t >= 1) ? xb[t - 1] : 0.f;
    float x2 = xb[t];
    g_hA[bt * NC + c] = w[c * 3 + 0] * x0 + w[c * 3 + 1] * x1 + w[c * 3 + 2] * x2 + b[c];
}

// ---------------- fused WaveNet block --------------------------------------
// y = W0 @ h[t-d] + W1 @ h[t] + cb ; skip = y[:128] * sigmoid(y[128:])
// h' = h + Wp @ skip + pb ; skip_sum (+)= skip
// FP32 FMA throughput doubled via packed fma.rn.f32x2 (pairs over t,t+1).

__global__ void __launch_bounds__(NTHREADS, 2)
layer_kernel(int l, int dil, int flip, int first,
             const float* __restrict__ conv_b,
             const float* __restrict__ post_b) {
    const float* __restrict__ h_in = flip ? g_hB : g_hA;
    float* __restrict__ h_out = flip ? g_hA : g_hB;

    extern __shared__ float sm[];
    float* Xc = sm;             // [64][128] current h tile
    float* Xp = sm + 8192;      // [64][128] prev (t-d) tile, reused as skip tile
    float* Wc = sm + 16384;     // [2 taps][8 k][256 o]
    float* Wp = sm + 20480;     // [8 k][128 o]

    int tid = threadIdx.x;
    int o_idx = tid & 31;
    int t_idx = tid >> 5;
    int c0 = o_idx * 4;
    int tr0 = t_idx * 8;

    int b = blockIdx.x >> 7;             // 128 tiles per batch
    int t0 = (blockIdx.x & 127) * TILE;
    const float* hin_t = h_in + (b * NT + t0) * NC;

    // stage Xc
    {
        const float4* src = (const float4*)hin_t;
        float4* dst = (float4*)Xc;
#pragma unroll
        for (int i = 0; i < 8; ++i) dst[tid + i * 256] = src[tid + i * 256];
    }
    // stage Xp (rows t0-d .. t0-d+63, zero for t<0)
    {
        int tp0 = t0 - dil;
        float4* dst = (float4*)Xp;
        const float4* base = (const float4*)(h_in + b * NT * NC);
#pragma unroll
        for (int i = 0; i < 8; ++i) {
            int e = tid + i * 256;
            int row = e >> 5;            // 32 float4 per row
            int tp = tp0 + row;
            float4 v = make_float4(0.f, 0.f, 0.f, 0.f);
            if (tp >= 0) v = base[tp * 32 + (e & 31)];
            dst[e] = v;
        }
    }

    const float* wconv_l = g_wconv + l * 65536;

    u64 acc2[8][4];  // 8 output rows x 4 t-pairs
    {
        u64 z = bcast2(0.f);
#pragma unroll
        for (int r = 0; r < 8; ++r)
#pragma unroll
            for (int t = 0; t < 4; ++t) acc2[r][t] = z;
    }

    // ---- conv GEMM: M=256(o), N=64(t), K=128, 2 taps, K chunked by 8 ----
    for (int kc = 0; kc < 16; ++kc) {
        __syncthreads();
        {
            const float4* s0 = (const float4*)(wconv_l + kc * 2048);
            const float4* s1 = (const float4*)(wconv_l + 32768 + kc * 2048);
            float4* d0 = (float4*)Wc;
            float4* d1 = (float4*)(Wc + 2048);
            d0[tid] = s0[tid];
            d0[tid + 256] = s0[tid + 256];
            d1[tid] = s1[tid];
            d1[tid + 256] = s1[tid + 256];
        }
        __syncthreads();
#pragma unroll
        for (int k = 0; k < 8; ++k) {
            int kk = kc * 8 + k;
            // x pairs (t, t+1) packed into 64-bit lanes
            u64 xp2[4], xc2[4];
#pragma unroll
            for (int t2 = 0; t2 < 4; ++t2) {
                int tt = tr0 + 2 * t2;
                xp2[t2] = pk2(Xp[tt * NC + kk], Xp[(tt + 1) * NC + kk]);
                xc2[t2] = pk2(Xc[tt * NC + kk], Xc[(tt + 1) * NC + kk]);
            }
            float4 w0a = *(float4*)&Wc[k * 256 + c0];
            float4 w0b = *(float4*)&Wc[k * 256 + 128 + c0];
            float4 w1a = *(float4*)&Wc[2048 + k * 256 + c0];
            float4 w1b = *(float4*)&Wc[2048 + k * 256 + 128 + c0];
            float wa[8], wb[8];
            wa[0] = w0a.x; wa[1] = w0a.y; wa[2] = w0a.z; wa[3] = w0a.w;
            wa[4] = w0b.x; wa[5] = w0b.y; wa[6] = w0b.z; wa[7] = w0b.w;
            wb[0] = w1a.x; wb[1] = w1a.y; wb[2] = w1a.z; wb[3] = w1a.w;
            wb[4] = w1b.x; wb[5] = w1b.y; wb[6] = w1b.z; wb[7] = w1b.w;
#pragma unroll
            for (int r = 0; r < 8; ++r) {
                u64 w0 = bcast2(wa[r]);
                u64 w1 = bcast2(wb[r]);
#pragma unroll
                for (int t2 = 0; t2 < 4; ++t2) {
                    acc2[r][t2] = ffma2(w0, xp2[t2], acc2[r][t2]);
                    acc2[r][t2] = ffma2(w1, xc2[t2], acc2[r][t2]);
                }
            }
        }
    }

    // ---- GLU (pairs held in-thread) + skip_sum ----
    float4 cba = *(const float4*)(conv_b + l * 256 + c0);
    float4 cbb = *(const float4*)(conv_b + l * 256 + 128 + c0);
    float ba[4] = {cba.x, cba.y, cba.z, cba.w};
    float bg[4] = {cbb.x, cbb.y, cbb.z, cbb.w};
    float sk[4][8];
#pragma unroll
    for (int r = 0; r < 4; ++r) {
#pragma unroll
        for (int t2 = 0; t2 < 4; ++t2) {
            float a_lo, a_hi, g_lo, g_hi;
            unpk2(acc2[r][t2], a_lo, a_hi);
            unpk2(acc2[r + 4][t2], g_lo, g_hi);
            a_lo += ba[r]; a_hi += ba[r];
            g_lo += bg[r]; g_hi += bg[r];
            sk[r][2 * t2]     = a_lo * (1.f / (1.f + __expf(-g_lo)));
            sk[r][2 * t2 + 1] = a_hi * (1.f / (1.f + __expf(-g_hi)));
        }
    }

    __syncthreads();  // all conv reads of Xp done; reuse as skip tile

    float* gsk = g_skip + (b * NT + t0) * NC;
#pragma unroll
    for (int t = 0; t < 8; ++t) {
        float4 s4 = make_float4(sk[0][t], sk[1][t], sk[2][t], sk[3][t]);
        *(float4*)&Xp[(tr0 + t) * NC + c0] = s4;
        float4* gp = (float4*)&gsk[(tr0 + t) * NC + c0];
        if (first) {
            *gp = s4;
        } else {
            float4 o = *gp;
            o.x += s4.x; o.y += s4.y; o.z += s4.z; o.w += s4.w;
            *gp = o;
        }
    }

    // ---- post GEMM: h' = h + Wp @ skip + pb ----
    const float* wpost_l = g_wpost + l * 16384;
    u64 accp2[4][4];
    {
        u64 z = bcast2(0.f);
#pragma unroll
        for (int r = 0; r < 4; ++r)
#pragma unroll
            for (int t = 0; t < 4; ++t) accp2[r][t] = z;
    }

    for (int kc = 0; kc < 16; ++kc) {
        __syncthreads();
        ((float4*)Wp)[tid] = ((const float4*)(wpost_l + kc * 1024))[tid];
        __syncthreads();
#pragma unroll
        for (int k = 0; k < 8; ++k) {
            int kk = kc * 8 + k;
            u64 xs2[4];
#pragma unroll
            for (int t2 = 0; t2 < 4; ++t2) {
                int tt = tr0 + 2 * t2;
                xs2[t2] = pk2(Xp[tt * NC + kk], Xp[(tt + 1) * NC + kk]);
            }
            float4 w4 = *(float4*)&Wp[k * 128 + c0];
            float wv[4] = {w4.x, w4.y, w4.z, w4.w};
#pragma unroll
            for (int r = 0; r < 4; ++r) {
                u64 wr = bcast2(wv[r]);
#pragma unroll
                for (int t2 = 0; t2 < 4; ++t2)
                    accp2[r][t2] = ffma2(wr, xs2[t2], accp2[r][t2]);
            }
        }
    }

    float4 pb = *(const float4*)(post_b + l * 128 + c0);
    float pbv[4] = {pb.x, pb.y, pb.z, pb.w};
    float* hout_t = h_out + (b * NT + t0) * NC;
#pragma unroll
    for (int t2 = 0; t2 < 4; ++t2) {
        int tt = tr0 + 2 * t2;
        float lo[4], hi[4];
#pragma unroll
        for (int r = 0; r < 4; ++r) unpk2(accp2[r][t2], lo[r], hi[r]);
        float4 hv0 = *(float4*)&Xc[tt * NC + c0];
        float4 hv1 = *(float4*)&Xc[(tt + 1) * NC + c0];
        float4 o0, o1;
        o0.x = hv0.x + lo[0] + pbv[0]; o0.y = hv0.y + lo[1] + pbv[1];
        o0.z = hv0.z + lo[2] + pbv[2]; o0.w = hv0.w + lo[3] + pbv[3];
        o1.x = hv1.x + hi[0] + pbv[0]; o1.y = hv1.y + hi[1] + pbv[1];
        o1.z = hv1.z + hi[2] + pbv[2]; o1.w = hv1.w + hi[3] + pbv[3];
        *(float4*)&hout_t[tt * NC + c0] = o0;
        *(float4*)&hout_t[(tt + 1) * NC + c0] = o1;
    }
}

// ---------------- final: relu -> lin1 -> relu -> lin2 -----------------------

__global__ void __launch_bounds__(NTHREADS, 2)
final_kernel(const float* __restrict__ lin1_b,
             const float* __restrict__ lin2_b,
             float* __restrict__ out) {
    extern __shared__ float sm[];
    float* Z = sm;            // [64][128]
    float* Z2 = sm + 8192;    // [64][128]
    float* Wl = sm + 16384;   // [8][128]

    int tid = threadIdx.x;
    int o_idx = tid & 31;
    int t_idx = tid >> 5;
    int c0 = o_idx * 4;
    int tr0 = t_idx * 8;

    int b = blockIdx.x >> 7;
    int t0 = (blockIdx.x & 127) * TILE;

    {
        const float4* src = (const float4*)(g_skip + (b * NT + t0) * NC);
        float4* dst = (float4*)Z;
#pragma unroll
        for (int i = 0; i < 8; ++i) {
            float4 v = src[tid + i * 256];
            v.x = fmaxf(v.x, 0.f); v.y = fmaxf(v.y, 0.f);
            v.z = fmaxf(v.z, 0.f); v.w = fmaxf(v.w, 0.f);
            dst[tid + i * 256] = v;
        }
    }

    u64 acc2[4][4];
    {
        u64 z = bcast2(0.f);
#pragma unroll
        for (int r = 0; r < 4; ++r)
#pragma unroll
            for (int t = 0; t < 4; ++t) acc2[r][t] = z;
    }

    for (int kc = 0; kc < 16; ++kc) {
        __syncthreads();
        ((float4*)Wl)[tid] = ((const float4*)(g_lin[0] + kc * 1024))[tid];
        __syncthreads();
#pragma unroll
        for (int k = 0; k < 8; ++k) {
            int kk = kc * 8 + k;
            u64 zz[4];
#pragma unroll
            for (int t2 = 0; t2 < 4; ++t2) {
                int tt = tr0 + 2 * t2;
                zz[t2] = pk2(Z[tt * NC + kk], Z[(tt + 1) * NC + kk]);
            }
            float4 w4 = *(float4*)&Wl[k * 128 + c0];
            float wv[4] = {w4.x, w4.y, w4.z, w4.w};
#pragma unroll
            for (int r = 0; r < 4; ++r) {
                u64 wr = bcast2(wv[r]);
#pragma unroll
                for (int t2 = 0; t2 < 4; ++t2)
                    acc2[r][t2] = ffma2(wr, zz[t2], acc2[r][t2]);
            }
        }
    }

    float4 b1 = *(const float4*)(lin1_b + c0);
    float b1v[4] = {b1.x, b1.y, b1.z, b1.w};
    __syncthreads();
#pragma unroll
    for (int t2 = 0; t2 < 4; ++t2) {
        int tt = tr0 + 2 * t2;
        float lo[4], hi[4];
#pragma unroll
        for (int r = 0; r < 4; ++r) unpk2(acc2[r][t2], lo[r], hi[r]);
        float4 z0, z1;
        z0.x = fmaxf(lo[0] + b1v[0], 0.f); z0.y = fmaxf(lo[1] + b1v[1], 0.f);
        z0.z = fmaxf(lo[2] + b1v[2], 0.f); z0.w = fmaxf(lo[3] + b1v[3], 0.f);
        z1.x = fmaxf(hi[0] + b1v[0], 0.f); z1.y = fmaxf(hi[1] + b1v[1], 0.f);
        z1.z = fmaxf(hi[2] + b1v[2], 0.f); z1.w = fmaxf(hi[3] + b1v[3], 0.f);
        *(float4*)&Z2[tt * NC + c0] = z0;
        *(float4*)&Z2[(tt + 1) * NC + c0] = z1;
    }

    u64 accb2[4][4];
    {
        u64 z = bcast2(0.f);
#pragma unroll
        for (int r = 0; r < 4; ++r)
#pragma unroll
            for (int t = 0; t < 4; ++t) accb2[r][t] = z;
    }

    for (int kc = 0; kc < 16; ++kc) {
        __syncthreads();
        ((float4*)Wl)[tid] = ((const float4*)(g_lin[1] + kc * 1024))[tid];
        __syncthreads();
#pragma unroll
        for (int k = 0; k < 8; ++k) {
            int kk = kc * 8 + k;
            u64 zz[4];
#pragma unroll
            for (int t2 = 0; t2 < 4; ++t2) {
                int tt = tr0 + 2 * t2;
                zz[t2] = pk2(Z2[tt * NC + kk], Z2[(tt + 1) * NC + kk]);
            }
            float4 w4 = *(float4*)&Wl[k * 128 + c0];
            float wv[4] = {w4.x, w4.y, w4.z, w4.w};
#pragma unroll
            for (int r = 0; r < 4; ++r) {
                u64 wr = bcast2(wv[r]);
#pragma unroll
                for (int t2 = 0; t2 < 4; ++t2)
                    accb2[r][t2] = ffma2(wr, zz[t2], accb2[r][t2]);
            }
        }
    }

    float4 b2 = *(const float4*)(lin2_b + c0);
    float b2v[4] = {b2.x, b2.y, b2.z, b2.w};
#pragma unroll
    for (int t2 = 0; t2 < 4; ++t2) {
        int tt = tr0 + 2 * t2;
        float lo[4], hi[4];
#pragma unroll
        for (int r = 0; r < 4; ++r) unpk2(accb2[r][t2], lo[r], hi[r]);
        float4 o0, o1;
        o0.x = lo[0] + b2v[0]; o0.y = lo[1] + b2v[1];
        o0.z = lo[2] + b2v[2]; o0.w = lo[3] + b2v[3];
        o1.x = hi[0] + b2v[0]; o1.y = hi[1] + b2v[1];
        o1.z = hi[2] + b2v[2]; o1.w = hi[3] + b2v[3];
        // out layout: [T][B][C]
        *(float4*)&out[((t0 + tt) * NB + b) * NC + c0] = o0;
        *(float4*)&out[((t0 + tt + 1) * NB + b) * NC + c0] = o1;
    }
}

// ---------------- launch -----------------------------------------------------

extern "C" void kernel_launch(void* const* d_in, const int* in_sizes, int n_in,
                              void* d_out, int out_size) {
    const float* x      = (const float*)d_in[0];
    const float* pre_w  = (const float*)d_in[1];
    const float* pre_b  = (const float*)d_in[2];
    const float* conv_w = (const float*)d_in[3];
    const float* conv_b = (const float*)d_in[4];
    const float* post_w = (const float*)d_in[5];
    const float* post_b = (const float*)d_in[6];
    const float* lin1_w = (const float*)d_in[7];
    const float* lin1_b = (const float*)d_in[8];
    const float* lin2_w = (const float*)d_in[9];
    const float* lin2_b = (const float*)d_in[10];

    cudaFuncSetAttribute(layer_kernel, cudaFuncAttributeMaxDynamicSharedMemorySize, 86016);
    cudaFuncSetAttribute(final_kernel, cudaFuncAttributeMaxDynamicSharedMemorySize, 69632);

    // weight transposes (cheap, deterministic each launch)
    tconv_kernel<<<10240, 256>>>(conv_w);   // 40*256*128*2 / 256
    tpost_kernel<<<2560, 256>>>(post_w);    // 40*128*128 / 256
    tlin_kernel<<<64, 256>>>(lin1_w, 0);
    tlin_kernel<<<64, 256>>>(lin2_w, 1);

    pre_kernel<<<NB * NT, 128>>>(x, pre_w, pre_b);

    for (int i = 0; i < NL; ++i) {
        int d = 1 << (i % 10);
        layer_kernel<<<512, NTHREADS, 86016>>>(i, d, i & 1, (i == 0) ? 1 : 0,
                                               conv_b, post_b);
    }

    final_kernel<<<512, NTHREADS, 69632>>>(lin1_b, lin2_b, (float*)d_out);
}

// round 7
// speedup vs baseline: 2.5444x; 2.5444x over previous
#include <cuda_runtime.h>

typedef unsigned int u32;

#define NB 4
#define NT 8192
#define NC 128
#define NL 40

// ---------------- persistent device scratch ----------------
__device__ float g_hA[NB * NT * NC];
__device__ float g_hB[NB * NT * NC];
__device__ float g_skip[NB * NT * NC];
__device__ float g_wconv[NL * 256 * 256];  // [l][kg(256)][o'(256)], o' interleaved filter/gate
__device__ float g_wpost[NL * 128 * 128];  // [l][k(128)][o(128)]
__device__ float g_lin[2 * 128 * 128];     // [which][k][o]

// ---------------- helpers ----------------
__device__ __forceinline__ float tf32r(float x) {
    u32 u;
    asm("cvt.rna.tf32.f32 %0, %1;" : "=r"(u) : "f"(x));
    return __uint_as_float(u);
}

__device__ __forceinline__ void mma8(float c[4], const u32 a[4], u32 b0, u32 b1) {
    asm volatile(
        "mma.sync.aligned.m16n8k8.row.col.f32.tf32.tf32.f32 "
        "{%0,%1,%2,%3}, {%4,%5,%6,%7}, {%8,%9}, {%0,%1,%2,%3};"
        : "+f"(c[0]), "+f"(c[1]), "+f"(c[2]), "+f"(c[3])
        : "r"(a[0]), "r"(a[1]), "r"(a[2]), "r"(a[3]), "r"(b0), "r"(b1));
}

// ---------------- weight transposes (tf32-rounded) ----------------

__global__ void tconv_kernel(const float* __restrict__ w) {
    // w: [L][256 og][128 c][2 tap] -> g_wconv[l][kg][o']
    int idx = blockIdx.x * blockDim.x + threadIdx.x;  // NL*256*128*2
    int tap = idx & 1;
    int c = (idx >> 1) & 127;
    int og = (idx >> 8) & 255;
    int l = idx >> 16;
    int kg = tap * 128 + c;                       // K: 0-127 = h[t-d], 128-255 = h[t]
    int op = (og < 128) ? (og * 2) : ((og - 128) * 2 + 1);  // interleave filter/gate
    g_wconv[l * 65536 + kg * 256 + op] = tf32r(w[idx]);
}

__global__ void tpost_kernel(const float* __restrict__ w) {
    // w: [L][128 o][128 c] -> [l][c][o]
    int idx = blockIdx.x * blockDim.x + threadIdx.x;  // NL*128*128
    int c = idx & 127;
    int o = (idx >> 7) & 127;
    int l = idx >> 14;
    g_wpost[l * 16384 + c * 128 + o] = tf32r(w[idx]);
}

__global__ void tlin_kernel(const float* __restrict__ w, int which) {
    // w: [128 o][128 i] -> [i][o]
    int idx = blockIdx.x * blockDim.x + threadIdx.x;  // 128*128
    int i = idx & 127;
    int o = idx >> 7;
    g_lin[which * 16384 + i * 128 + o] = tf32r(w[idx]);
}

// ---------------- pre-net ----------------

__global__ void pre_kernel(const float* __restrict__ x,
                           const float* __restrict__ w,
                           const float* __restrict__ b) {
    int bt = blockIdx.x;
    int bb = bt >> 13;
    int t = bt & 8191;
    int c = threadIdx.x;
    const float* xb = x + bb * NT;
    float x0 = (t >= 2) ? xb[t - 2] : 0.f;
    float x1 = (t >= 1) ? xb[t - 1] : 0.f;
    float x2 = xb[t];
    g_hA[bt * NC + c] = w[c * 3 + 0] * x0 + w[c * 3 + 1] * x1 + w[c * 3 + 2] * x2 + b[c];
}

// ---------------- fused WaveNet block (mma.sync tf32) -----------------------
// smem floats: XP[64][132] @0, XC[64][132] @8448, WB @16896 (2 conv bufs of
// 32*264=8448; post reuses 2 bufs of 32*136=4352), CBS @33792, PBS @34048.
// Warp grid 2(M)x4(N); fragments per PTX m16n8k8 tf32 layout.

__global__ void __launch_bounds__(256, 1)
layer_kernel(int l, int dil, int flip, int first,
             const float* __restrict__ conv_b,
             const float* __restrict__ post_b) {
    const float* __restrict__ h_in = flip ? g_hB : g_hA;
    float* __restrict__ h_out = flip ? g_hA : g_hB;

    extern __shared__ float sm[];
    float* XP = sm;
    float* XC = sm + 8448;
    float* WB = sm + 16896;
    float* CBS = sm + 33792;
    float* PBS = sm + 34048;

    int tid = threadIdx.x;
    int lane = tid & 31, wid = tid >> 5;
    int g = lane >> 2, tig = lane & 3;
    int m_idx = wid >> 2, n_idx = wid & 3;

    int b = blockIdx.x >> 7;
    int t0 = (blockIdx.x & 127) << 6;

    // biases: conv bias interleaved to match o' ordering
    CBS[tid] = conv_b[l * 256 + ((tid & 1) ? 128 + (tid >> 1) : (tid >> 1))];
    if (tid < 128) PBS[tid] = post_b[l * 128 + tid];

    // stage X tiles (tf32-rounded)
    const float* hb = h_in + (size_t)b * NT * NC;
#pragma unroll
    for (int i = 0; i < 8; i++) {
        int e = tid + i * 256;
        int row = e >> 5, q = e & 31;
        float4 v = *(const float4*)(hb + (size_t)(t0 + row) * NC + q * 4);
        v.x = tf32r(v.x); v.y = tf32r(v.y); v.z = tf32r(v.z); v.w = tf32r(v.w);
        *(float4*)(XC + row * 132 + q * 4) = v;
        int tp = t0 + row - dil;
        float4 u = make_float4(0.f, 0.f, 0.f, 0.f);
        if (tp >= 0) {
            u = *(const float4*)(hb + (size_t)tp * NC + q * 4);
            u.x = tf32r(u.x); u.y = tf32r(u.y); u.z = tf32r(u.z); u.w = tf32r(u.w);
        }
        *(float4*)(XP + row * 132 + q * 4) = u;
    }

    float acc[2][8][4];
#pragma unroll
    for (int mt = 0; mt < 2; mt++)
#pragma unroll
        for (int nt = 0; nt < 8; nt++)
#pragma unroll
            for (int j = 0; j < 4; j++) acc[mt][nt][j] = 0.f;

    // ---- conv GEMM: C[64t, 256o'] += X[64, 256] * W[256, 256] ----
    const float* wcl = g_wconv + (size_t)l * 65536;
    for (int kc = 0; kc < 8; kc++) {
        const float4* src = (const float4*)(wcl + kc * 8192);
        float* dw = WB + (kc & 1) * 8448;
#pragma unroll
        for (int i = 0; i < 8; i++) {
            int e = tid + i * 256;
            int row = e >> 6, q = e & 63;
            *(float4*)(dw + row * 264 + q * 4) = src[e];
        }
        __syncthreads();
        const u32* Xu = (const u32*)((kc < 4) ? XP : XC);
        const u32* Wu = (const u32*)dw;
        int kb = (kc & 3) * 32;
#pragma unroll
        for (int ks = 0; ks < 4; ks++) {
            int kloc = kb + ks * 8 + tig;
            u32 A[2][4];
#pragma unroll
            for (int mt = 0; mt < 2; mt++) {
                int r = m_idx * 32 + mt * 16 + g;
                A[mt][0] = Xu[r * 132 + kloc];
                A[mt][1] = Xu[(r + 8) * 132 + kloc];
                A[mt][2] = Xu[r * 132 + kloc + 4];
                A[mt][3] = Xu[(r + 8) * 132 + kloc + 4];
            }
#pragma unroll
            for (int nt = 0; nt < 8; nt++) {
                int n = n_idx * 64 + nt * 8 + g;
                u32 B0 = Wu[(ks * 8 + tig) * 264 + n];
                u32 B1 = Wu[(ks * 8 + tig + 4) * 264 + n];
                mma8(acc[0][nt], A[0], B0, B1);
                mma8(acc[1][nt], A[1], B0, B1);
            }
        }
    }

    __syncthreads();  // all conv reads of XP done; XP becomes the skip tile

    // ---- GLU epilogue: skip = a * sigmoid(gate); skip_sum; skip->smem ----
    float* gsk = g_skip + ((size_t)b * NT + t0) * NC;
#pragma unroll
    for (int mt = 0; mt < 2; mt++) {
#pragma unroll
        for (int nt = 0; nt < 8; nt++) {
            int o0 = n_idx * 64 + nt * 8 + tig * 2;
            int ch = o0 >> 1;
            float cb0 = CBS[o0], cb1 = CBS[o0 + 1];
            int r0 = m_idx * 32 + mt * 16 + g;
            float a0 = acc[mt][nt][0] + cb0, g0 = acc[mt][nt][1] + cb1;
            float a1 = acc[mt][nt][2] + cb0, g1 = acc[mt][nt][3] + cb1;
            float s0 = a0 / (1.f + __expf(-g0));
            float s1 = a1 / (1.f + __expf(-g1));
            if (first) {
                gsk[r0 * NC + ch] = s0;
                gsk[(r0 + 8) * NC + ch] = s1;
            } else {
                gsk[r0 * NC + ch] += s0;
                gsk[(r0 + 8) * NC + ch] += s1;
            }
            XP[r0 * 132 + ch] = tf32r(s0);
            XP[(r0 + 8) * 132 + ch] = tf32r(s1);
        }
    }
    __syncthreads();

    // ---- post GEMM: D[64t,128o] = skip[64,128] * Wp[128,128] ----
    float accp[2][4][4];
#pragma unroll
    for (int mt = 0; mt < 2; mt++)
#pragma unroll
        for (int nt = 0; nt < 4; nt++)
#pragma unroll
            for (int j = 0; j < 4; j++) accp[mt][nt][j] = 0.f;

    const float* wpl = g_wpost + (size_t)l * 16384;
    for (int kc = 0; kc < 4; kc++) {
        const float4* src = (const float4*)(wpl + kc * 4096);
        float* dw = WB + (kc & 1) * 4352;
#pragma unroll
        for (int i = 0; i < 4; i++) {
            int e = tid + i * 256;
            int row = e >> 5, q = e & 31;
            *(float4*)(dw + row * 136 + q * 4) = src[e];
        }
        __syncthreads();
        const u32* Su = (const u32*)XP;
        const u32* Wu = (const u32*)dw;
#pragma unroll
        for (int ks = 0; ks < 4; ks++) {
            int kloc = kc * 32 + ks * 8 + tig;
            u32 A[2][4];
#pragma unroll
            for (int mt = 0; mt < 2; mt++) {
                int r = m_idx * 32 + mt * 16 + g;
                A[mt][0] = Su[r * 132 + kloc];
                A[mt][1] = Su[(r + 8) * 132 + kloc];
                A[mt][2] = Su[r * 132 + kloc + 4];
                A[mt][3] = Su[(r + 8) * 132 + kloc + 4];
            }
#pragma unroll
            for (int nt = 0; nt < 4; nt++) {
                int n = n_idx * 32 + nt * 8 + g;
                u32 B0 = Wu[(ks * 8 + tig) * 136 + n];
                u32 B1 = Wu[(ks * 8 + tig + 4) * 136 + n];
                mma8(accp[0][nt], A[0], B0, B1);
                mma8(accp[1][nt], A[1], B0, B1);
            }
        }
    }

    // ---- residual epilogue (fp32 h path) ----
    const float* hres = h_in + ((size_t)b * NT + t0) * NC;
    float* hdst = h_out + ((size_t)b * NT + t0) * NC;
#pragma unroll
    for (int mt = 0; mt < 2; mt++) {
#pragma unroll
        for (int nt = 0; nt < 4; nt++) {
            int o0 = n_idx * 32 + nt * 8 + tig * 2;
            int r0 = m_idx * 32 + mt * 16 + g;
            float pb0 = PBS[o0], pb1 = PBS[o0 + 1];
            float2 h0 = *(const float2*)(hres + r0 * NC + o0);
            float2 h1 = *(const float2*)(hres + (r0 + 8) * NC + o0);
            float2 v0, v1;
            v0.x = h0.x + accp[mt][nt][0] + pb0;
            v0.y = h0.y + accp[mt][nt][1] + pb1;
            v1.x = h1.x + accp[mt][nt][2] + pb0;
            v1.y = h1.y + accp[mt][nt][3] + pb1;
            *(float2*)(hdst + r0 * NC + o0) = v0;
            *(float2*)(hdst + (r0 + 8) * NC + o0) = v1;
        }
    }
}

// ---------------- final: relu -> lin1 -> relu -> lin2 -----------------------
// smem floats: Z[64][132] @0, WB @8448 (2 bufs 32*136=4352), B1S @17152, B2S @17280

__global__ void __launch_bounds__(256, 1)
final_kernel(const float* __restrict__ lin1_b,
             const float* __restrict__ lin2_b,
             float* __restrict__ out) {
    extern __shared__ float sm[];
    float* Z = sm;
    float* WB = sm + 8448;
    float* B1S = sm + 17152;
    float* B2S = sm + 17280;

    int tid = threadIdx.x;
    int lane = tid & 31, wid = tid >> 5;
    int g = lane >> 2, tig = lane & 3;
    int m_idx = wid >> 2, n_idx = wid & 3;

    int b = blockIdx.x >> 7;
    int t0 = (blockIdx.x & 127) << 6;

    if (tid < 128) {
        B1S[tid] = lin1_b[tid];
        B2S[tid] = lin2_b[tid];
    }

    // stage Z = tf32(relu(skip_sum))
    const float* zb = g_skip + ((size_t)b * NT + t0) * NC;
#pragma unroll
    for (int i = 0; i < 8; i++) {
        int e = tid + i * 256;
        int row = e >> 5, q = e & 31;
        float4 v = *(const float4*)(zb + (size_t)row * NC + q * 4);
        v.x = tf32r(fmaxf(v.x, 0.f)); v.y = tf32r(fmaxf(v.y, 0.f));
        v.z = tf32r(fmaxf(v.z, 0.f)); v.w = tf32r(fmaxf(v.w, 0.f));
        *(float4*)(Z + row * 132 + q * 4) = v;
    }

    for (int pass = 0; pass < 2; pass++) {
        float acc[2][4][4];
#pragma unroll
        for (int mt = 0; mt < 2; mt++)
#pragma unroll
            for (int nt = 0; nt < 4; nt++)
#pragma unroll
                for (int j = 0; j < 4; j++) acc[mt][nt][j] = 0.f;

        const float* wl = g_lin + pass * 16384;
        for (int kc = 0; kc < 4; kc++) {
            const float4* src = (const float4*)(wl + kc * 4096);
            float* dw = WB + (kc & 1) * 4352;
#pragma unroll
            for (int i = 0; i < 4; i++) {
                int e = tid + i * 256;
                int row = e >> 5, q = e & 31;
                *(float4*)(dw + row * 136 + q * 4) = src[e];
            }
            __syncthreads();
            const u32* Su = (const u32*)Z;
            const u32* Wu = (const u32*)dw;
#pragma unroll
            for (int ks = 0; ks < 4; ks++) {
                int kloc = kc * 32 + ks * 8 + tig;
                u32 A[2][4];
#pragma unroll
                for (int mt = 0; mt < 2; mt++) {
                    int r = m_idx * 32 + mt * 16 + g;
                    A[mt][0] = Su[r * 132 + kloc];
                    A[mt][1] = Su[(r + 8) * 132 + kloc];
                    A[mt][2] = Su[r * 132 + kloc + 4];
                    A[mt][3] = Su[(r + 8) * 132 + kloc + 4];
                }
#pragma unroll
                for (int nt = 0; nt < 4; nt++) {
                    int n = n_idx * 32 + nt * 8 + g;
                    u32 B0 = Wu[(ks * 8 + tig) * 136 + n];
                    u32 B1 = Wu[(ks * 8 + tig + 4) * 136 + n];
                    mma8(acc[0][nt], A[0], B0, B1);
                    mma8(acc[1][nt], A[1], B0, B1);
                }
            }
        }

        if (pass == 0) {
            __syncthreads();  // all lin1 reads of Z done
#pragma unroll
            for (int mt = 0; mt < 2; mt++) {
#pragma unroll
                for (int nt = 0; nt < 4; nt++) {
                    int o0 = n_idx * 32 + nt * 8 + tig * 2;
                    int r0 = m_idx * 32 + mt * 16 + g;
                    float b0 = B1S[o0], b1 = B1S[o0 + 1];
                    Z[r0 * 132 + o0]           = tf32r(fmaxf(acc[mt][nt][0] + b0, 0.f));
                    Z[r0 * 132 + o0 + 1]       = tf32r(fmaxf(acc[mt][nt][1] + b1, 0.f));
                    Z[(r0 + 8) * 132 + o0]     = tf32r(fmaxf(acc[mt][nt][2] + b0, 0.f));
                    Z[(r0 + 8) * 132 + o0 + 1] = tf32r(fmaxf(acc[mt][nt][3] + b1, 0.f));
                }
            }
            __syncthreads();
        } else {
            // out layout [T][B][C]
#pragma unroll
            for (int mt = 0; mt < 2; mt++) {
#pragma unroll
                for (int nt = 0; nt < 4; nt++) {
                    int o0 = n_idx * 32 + nt * 8 + tig * 2;
                    int r0 = m_idx * 32 + mt * 16 + g;
                    float b0 = B2S[o0], b1 = B2S[o0 + 1];
                    float2 v0, v1;
                    v0.x = acc[mt][nt][0] + b0;
                    v0.y = acc[mt][nt][1] + b1;
                    v1.x = acc[mt][nt][2] + b0;
                    v1.y = acc[mt][nt][3] + b1;
                    *(float2*)(out + ((size_t)(t0 + r0) * NB + b) * NC + o0) = v0;
                    *(float2*)(out + ((size_t)(t0 + r0 + 8) * NB + b) * NC + o0) = v1;
                }
            }
        }
    }
}

// ---------------- launch -----------------------------------------------------

#define SMEM_LAYER (34176 * 4)
#define SMEM_FINAL (17408 * 4)

extern "C" void kernel_launch(void* const* d_in, const int* in_sizes, int n_in,
                              void* d_out, int out_size) {
    const float* x      = (const float*)d_in[0];
    const float* pre_w  = (const float*)d_in[1];
    const float* pre_b  = (const float*)d_in[2];
    const float* conv_w = (const float*)d_in[3];
    const float* conv_b = (const float*)d_in[4];
    const float* post_w = (const float*)d_in[5];
    const float* post_b = (const float*)d_in[6];
    const float* lin1_w = (const float*)d_in[7];
    const float* lin1_b = (const float*)d_in[8];
    const float* lin2_w = (const float*)d_in[9];
    const float* lin2_b = (const float*)d_in[10];

    cudaFuncSetAttribute(layer_kernel, cudaFuncAttributeMaxDynamicSharedMemorySize, SMEM_LAYER);
    cudaFuncSetAttribute(final_kernel, cudaFuncAttributeMaxDynamicSharedMemorySize, SMEM_FINAL);

    tconv_kernel<<<10240, 256>>>(conv_w);
    tpost_kernel<<<2560, 256>>>(post_w);
    tlin_kernel<<<64, 256>>>(lin1_w, 0);
    tlin_kernel<<<64, 256>>>(lin2_w, 1);

    pre_kernel<<<NB * NT, 128>>>(x, pre_w, pre_b);

    for (int i = 0; i < NL; ++i) {
        int d = 1 << (i % 10);
        layer_kernel<<<512, 256, SMEM_LAYER>>>(i, d, i & 1, (i == 0) ? 1 : 0,
                                               conv_b, post_b);
    }

    final_kernel<<<512, 256, SMEM_FINAL>>>(lin1_b, lin2_b, (float*)d_out);
}

// round 10
// speedup vs baseline: 4.9902x; 1.9613x over previous
#include <cuda_runtime.h>
#include <cuda_fp16.h>

typedef unsigned int u32;

#define NB 4
#define NT 8192
#define NC 128
#define NL 40

// ---------------- persistent device scratch ----------------
__device__ float g_hA[NB * NT * NC];
__device__ float g_hB[NB * NT * NC];
__device__ float g_skip[NB * NT * NC];
// padded smem-image layouts (half):
// conv: [l][8 chunks][256 o'][40]  (32 k + 8 pad), o' interleaved filter/gate
__device__ __align__(128) __half g_wconv_h[NL * 8 * 256 * 40];
// post: [l][2 chunks][128 o][72]   (64 k + 8 pad)
__device__ __align__(128) __half g_wpost_h[NL * 2 * 128 * 72];
// lin:  [which][2 chunks][128 o][72]
__device__ __align__(128) __half g_lin_h[2 * 2 * 128 * 72];

// ---------------- helpers ----------------
__device__ __forceinline__ u32 smem_u32(const void* p) {
    u32 a;
    asm("{ .reg .u64 t; cvta.to.shared.u64 t, %1; cvt.u32.u64 %0, t; }" : "=r"(a) : "l"(p));
    return a;
}
__device__ __forceinline__ void cpa16(u32 dst, const void* src) {
    asm volatile("cp.async.cg.shared.global [%0], [%1], 16;" :: "r"(dst), "l"(src));
}
#define CP_COMMIT() asm volatile("cp.async.commit_group;" ::: "memory")
#define CP_WAIT0() asm volatile("cp.async.wait_group 0;" ::: "memory")
#define CP_WAIT1() asm volatile("cp.async.wait_group 1;" ::: "memory")

__device__ __forceinline__ void mma16(float c[4], const u32 a[4], u32 b0, u32 b1) {
    asm volatile(
        "mma.sync.aligned.m16n8k16.row.col.f32.f16.f16.f32 "
        "{%0,%1,%2,%3}, {%4,%5,%6,%7}, {%8,%9}, {%0,%1,%2,%3};"
        : "+f"(c[0]), "+f"(c[1]), "+f"(c[2]), "+f"(c[3])
        : "r"(a[0]), "r"(a[1]), "r"(a[2]), "r"(a[3]), "r"(b0), "r"(b1));
}

// ---------------- weight transposes (fp16, padded images) -------------------

__global__ void tconv_kernel(const float* __restrict__ w) {
    // w: [L][256 og][128 c][2 tap]
    int idx = blockIdx.x * blockDim.x + threadIdx.x;  // NL*256*128*2
    int tap = idx & 1;
    int c = (idx >> 1) & 127;
    int og = (idx >> 8) & 255;
    int l = idx >> 16;
    int kg = tap * 128 + c;                    // K: 0-127 = h[t-d], 128-255 = h[t]
    int kc = kg >> 5, ki = kg & 31;
    int op = (og < 128) ? (og * 2) : ((og - 128) * 2 + 1);
    g_wconv_h[((l * 8 + kc) * 256 + op) * 40 + ki] = __float2half_rn(w[idx]);
}

__global__ void tpost_kernel(const float* __restrict__ w) {
    // w: [L][128 o][128 c]
    int idx = blockIdx.x * blockDim.x + threadIdx.x;  // NL*128*128
    int c = idx & 127;
    int o = (idx >> 7) & 127;
    int l = idx >> 14;
    g_wpost_h[((l * 2 + (c >> 6)) * 128 + o) * 72 + (c & 63)] = __float2half_rn(w[idx]);
}

__global__ void tlin_kernel(const float* __restrict__ w, int which) {
    // w: [128 o][128 i]
    int idx = blockIdx.x * blockDim.x + threadIdx.x;  // 128*128
    int i = idx & 127;
    int o = idx >> 7;
    g_lin_h[((which * 2 + (i >> 6)) * 128 + o) * 72 + (i & 63)] = __float2half_rn(w[idx]);
}

// ---------------- pre-net ----------------

__global__ void pre_kernel(const float* __restrict__ x,
                           const float* __restrict__ w,
                           const float* __restrict__ b) {
    int bt = blockIdx.x;
    int bb = bt >> 13;
    int t = bt & 8191;
    int c = threadIdx.x;
    const float* xb = x + bb * NT;
    float x0 = (t >= 2) ? xb[t - 2] : 0.f;
    float x1 = (t >= 1) ? xb[t - 1] : 0.f;
    float x2 = xb[t];
    g_hA[bt * NC + c] = w[c * 3 + 0] * x0 + w[c * 3 + 1] * x1 + w[c * 3 + 2] * x2 + b[c];
}

// ---------------- fused WaveNet block (fp16 mma + cp.async) -----------------
// smem bytes: X [64][264] half @0 (33792); WB @33792 (40960: conv 2x10240h,
//             post reuses 2x9216h); CBS @74752 (1024); PBS @75776 (512).

#define XO_B 0
#define WB_B 33792
#define CB_B 74752
#define PB_B 75776
#define SMEM_LAYER 76288
#define XS 264

__global__ void __launch_bounds__(256, 2)
layer_kernel(int l, int dil, int flip, int first,
             const float* __restrict__ conv_b,
             const float* __restrict__ post_b) {
    const float* __restrict__ h_in = flip ? g_hB : g_hA;
    float* __restrict__ h_out = flip ? g_hA : g_hB;

    extern __shared__ char smx[];
    __half* X = (__half*)smx;
    __half* WB = (__half*)(smx + WB_B);
    float* CBS = (float*)(smx + CB_B);
    float* PBS = (float*)(smx + PB_B);
    u32 smb = smem_u32(smx);

    int tid = threadIdx.x;
    int lane = tid & 31, wid = tid >> 5;
    int g = lane >> 2, tig = lane & 3;
    int m_idx = wid >> 2, n_idx = wid & 3;

    int b = blockIdx.x >> 7;
    int t0 = (blockIdx.x & 127) << 6;

    const char* wcl = (const char*)(g_wconv_h) + (size_t)l * 163840;

    // preload conv chunk 0 (overlaps X staging)
    {
        u32 d = smb + WB_B;
#pragma unroll
        for (int j = 0; j < 5; j++)
            cpa16(d + (tid + j * 256) * 16, wcl + (tid + j * 256) * 16);
        CP_COMMIT();
    }

    // biases (conv bias interleaved to o' order)
    CBS[tid] = conv_b[l * 256 + ((tid & 1) ? 128 + (tid >> 1) : (tid >> 1))];
    if (tid < 128) PBS[tid] = post_b[l * 128 + tid];

    // stage X: [64 rows][256 k] fp16 ; k 0-127 = h[t-d], 128-255 = h[t]
    const float* hb = h_in + (size_t)b * NT * NC;
#pragma unroll
    for (int i = 0; i < 16; i++) {
        int e = tid + i * 256;
        int row = e >> 6, q = e & 63;
        float4 v = make_float4(0.f, 0.f, 0.f, 0.f);
        if (q < 32) {
            int tp = t0 + row - dil;
            if (tp >= 0) v = *(const float4*)(hb + (size_t)tp * NC + q * 4);
        } else {
            v = *(const float4*)(hb + (size_t)(t0 + row) * NC + (q - 32) * 4);
        }
        __half2 p0 = __floats2half2_rn(v.x, v.y);
        __half2 p1 = __floats2half2_rn(v.z, v.w);
        *(__half2*)(X + row * XS + q * 4) = p0;
        *(__half2*)(X + row * XS + q * 4 + 2) = p1;
    }

    float acc[2][8][4];
#pragma unroll
    for (int mt = 0; mt < 2; mt++)
#pragma unroll
        for (int nt = 0; nt < 8; nt++)
#pragma unroll
            for (int j = 0; j < 4; j++) acc[mt][nt][j] = 0.f;

    // ---- conv GEMM: C[64t, 256o'] = X[64,256] * W[256,256], 8 k-chunks ----
    for (int kc = 0; kc < 8; kc++) {
        if (kc < 7) {
            u32 d = smb + WB_B + ((kc + 1) & 1) * 20480;
            const char* s = wcl + (kc + 1) * 20480;
#pragma unroll
            for (int j = 0; j < 5; j++)
                cpa16(d + (tid + j * 256) * 16, s + (tid + j * 256) * 16);
            CP_COMMIT();
            CP_WAIT1();
        } else {
            CP_WAIT0();
        }
        __syncthreads();
        const __half* Wc = WB + (kc & 1) * 10240;
#pragma unroll
        for (int ks = 0; ks < 2; ks++) {
            int kcol = kc * 32 + ks * 16 + tig * 2;
            u32 A[2][4];
#pragma unroll
            for (int mt = 0; mt < 2; mt++) {
                int r = m_idx * 32 + mt * 16 + g;
                A[mt][0] = *(const u32*)(X + r * XS + kcol);
                A[mt][1] = *(const u32*)(X + (r + 8) * XS + kcol);
                A[mt][2] = *(const u32*)(X + r * XS + kcol + 8);
                A[mt][3] = *(const u32*)(X + (r + 8) * XS + kcol + 8);
            }
#pragma unroll
            for (int nt = 0; nt < 8; nt++) {
                int n = n_idx * 64 + nt * 8 + g;
                u32 B0 = *(const u32*)(Wc + n * 40 + ks * 16 + tig * 2);
                u32 B1 = *(const u32*)(Wc + n * 40 + ks * 16 + tig * 2 + 8);
                mma16(acc[0][nt], A[0], B0, B1);
                mma16(acc[1][nt], A[1], B0, B1);
            }
        }
        __syncthreads();  // protect buffer reuse by next iteration's cp.async
    }

    // preload both post-W chunks (overlap with GLU epilogue)
    {
        const char* wpl = (const char*)(g_wpost_h) + (size_t)l * 36864;
#pragma unroll
        for (int pc = 0; pc < 2; pc++) {
            u32 d = smb + WB_B + pc * 18432;
            const char* s = wpl + pc * 18432;
#pragma unroll
            for (int j = 0; j < 5; j++) {
                int e = tid + j * 256;
                if (e < 1152) cpa16(d + e * 16, s + e * 16);
            }
            CP_COMMIT();
        }
    }

    // ---- GLU epilogue: skip = a * sigmoid(gate); skip_sum; skip -> X[:,0:128]
    float* gsk = g_skip + ((size_t)b * NT + t0) * NC;
#pragma unroll
    for (int mt = 0; mt < 2; mt++) {
#pragma unroll
        for (int nt = 0; nt < 8; nt++) {
            int o0 = n_idx * 64 + nt * 8 + tig * 2;
            int ch = o0 >> 1;
            float cb0 = CBS[o0], cb1 = CBS[o0 + 1];
            int r0 = m_idx * 32 + mt * 16 + g;
            float a0 = acc[mt][nt][0] + cb0, g0 = acc[mt][nt][1] + cb1;
            float a1 = acc[mt][nt][2] + cb0, g1 = acc[mt][nt][3] + cb1;
            float s0 = a0 / (1.f + __expf(-g0));
            float s1 = a1 / (1.f + __expf(-g1));
            if (first) {
                gsk[r0 * NC + ch] = s0;
                gsk[(r0 + 8) * NC + ch] = s1;
            } else {
                gsk[r0 * NC + ch] += s0;
                gsk[(r0 + 8) * NC + ch] += s1;
            }
            X[r0 * XS + ch] = __float2half_rn(s0);
            X[(r0 + 8) * XS + ch] = __float2half_rn(s1);
        }
    }

    // ---- post GEMM: D[64t,128o] = skip[64,128] * Wp[128,128], 2 k-chunks ----
    float accp[2][4][4];
#pragma unroll
    for (int mt = 0; mt < 2; mt++)
#pragma unroll
        for (int nt = 0; nt < 4; nt++)
#pragma unroll
            for (int j = 0; j < 4; j++) accp[mt][nt][j] = 0.f;

#pragma unroll
    for (int pc = 0; pc < 2; pc++) {
        if (pc == 0) CP_WAIT1(); else CP_WAIT0();
        __syncthreads();  // copies visible + (pc==0) skip-tile stores visible
        const __half* Wp = WB + pc * 9216;
#pragma unroll
        for (int ks = 0; ks < 4; ks++) {
            int kcol = pc * 64 + ks * 16 + tig * 2;
            u32 A[2][4];
#pragma unroll
            for (int mt = 0; mt < 2; mt++) {
                int r = m_idx * 32 + mt * 16 + g;
                A[mt][0] = *(const u32*)(X + r * XS + kcol);
                A[mt][1] = *(const u32*)(X + (r + 8) * XS + kcol);
                A[mt][2] = *(const u32*)(X + r * XS + kcol + 8);
                A[mt][3] = *(const u32*)(X + (r + 8) * XS + kcol + 8);
            }
#pragma unroll
            for (int nt = 0; nt < 4; nt++) {
                int n = n_idx * 32 + nt * 8 + g;
                u32 B0 = *(const u32*)(Wp + n * 72 + ks * 16 + tig * 2);
                u32 B1 = *(const u32*)(Wp + n * 72 + ks * 16 + tig * 2 + 8);
                mma16(accp[0][nt], A[0], B0, B1);
                mma16(accp[1][nt], A[1], B0, B1);
            }
        }
    }

    // ---- residual epilogue (fp32 h path) ----
    const float* hres = h_in + ((size_t)b * NT + t0) * NC;
    float* hdst = h_out + ((size_t)b * NT + t0) * NC;
#pragma unroll
    for (int mt = 0; mt < 2; mt++) {
#pragma unroll
        for (int nt = 0; nt < 4; nt++) {
            int o0 = n_idx * 32 + nt * 8 + tig * 2;
            int r0 = m_idx * 32 + mt * 16 + g;
            float pb0 = PBS[o0], pb1 = PBS[o0 + 1];
            float2 h0 = *(const float2*)(hres + r0 * NC + o0);
            float2 h1 = *(const float2*)(hres + (r0 + 8) * NC + o0);
            float2 v0, v1;
            v0.x = h0.x + accp[mt][nt][0] + pb0;
            v0.y = h0.y + accp[mt][nt][1] + pb1;
            v1.x = h1.x + accp[mt][nt][2] + pb0;
            v1.y = h1.y + accp[mt][nt][3] + pb1;
            *(float2*)(hdst + r0 * NC + o0) = v0;
            *(float2*)(hdst + (r0 + 8) * NC + o0) = v1;
        }
    }
}

// ---------------- final: relu -> lin1 -> relu -> lin2 (fp16 mma) ------------
// smem bytes: Z [64][136] half @0 (17408); WB @17408 (2x9216h = 36864);
//             B1S @54272 (512); B2S @54784 (512). total 55296.

#define FZ_B 0
#define FWB_B 17408
#define FB1_B 54272
#define FB2_B 54784
#define SMEM_FINAL 55296
#define ZS 136

__global__ void __launch_bounds__(256, 2)
final_kernel(const float* __restrict__ lin1_b,
             const float* __restrict__ lin2_b,
             float* __restrict__ out) {
    extern __shared__ char smx[];
    __half* Z = (__half*)smx;
    __half* WB = (__half*)(smx + FWB_B);
    float* B1S = (float*)(smx + FB1_B);
    float* B2S = (float*)(smx + FB2_B);
    u32 smb = smem_u32(smx);

    int tid = threadIdx.x;
    int lane = tid & 31, wid = tid >> 5;
    int g = lane >> 2, tig = lane & 3;
    int m_idx = wid >> 2, n_idx = wid & 3;

    int b = blockIdx.x >> 7;
    int t0 = (blockIdx.x & 127) << 6;

    // preload lin1 chunks 0,1
#pragma unroll
    for (int pc = 0; pc < 2; pc++) {
        u32 d = smb + FWB_B + pc * 18432;
        const char* s = (const char*)(g_lin_h) + pc * 18432;
#pragma unroll
        for (int j = 0; j < 5; j++) {
            int e = tid + j * 256;
            if (e < 1152) cpa16(d + e * 16, s + e * 16);
        }
        CP_COMMIT();
    }

    if (tid < 128) {
        B1S[tid] = lin1_b[tid];
        B2S[tid] = lin2_b[tid];
    }

    // stage Z = fp16(relu(skip_sum))
    const float* zb = g_skip + ((size_t)b * NT + t0) * NC;
#pragma unroll
    for (int i = 0; i < 8; i++) {
        int e = tid + i * 256;
        int row = e >> 5, q = e & 31;
        float4 v = *(const float4*)(zb + (size_t)row * NC + q * 4);
        v.x = fmaxf(v.x, 0.f); v.y = fmaxf(v.y, 0.f);
        v.z = fmaxf(v.z, 0.f); v.w = fmaxf(v.w, 0.f);
        *(__half2*)(Z + row * ZS + q * 4) = __floats2half2_rn(v.x, v.y);
        *(__half2*)(Z + row * ZS + q * 4 + 2) = __floats2half2_rn(v.z, v.w);
    }

#pragma unroll
    for (int pass = 0; pass < 2; pass++) {
        float acc[2][4][4];
#pragma unroll
        for (int mt = 0; mt < 2; mt++)
#pragma unroll
            for (int nt = 0; nt < 4; nt++)
#pragma unroll
                for (int j = 0; j < 4; j++) acc[mt][nt][j] = 0.f;

#pragma unroll
        for (int pc = 0; pc < 2; pc++) {
            if (pc == 0) CP_WAIT1(); else CP_WAIT0();
            __syncthreads();
            const __half* Wp = WB + pc * 9216;
#pragma unroll
            for (int ks = 0; ks < 4; ks++) {
                int kcol = pc * 64 + ks * 16 + tig * 2;
                u32 A[2][4];
#pragma unroll
                for (int mt = 0; mt < 2; mt++) {
                    int r = m_idx * 32 + mt * 16 + g;
                    A[mt][0] = *(const u32*)(Z + r * ZS + kcol);
                    A[mt][1] = *(const u32*)(Z + (r + 8) * ZS + kcol);
                    A[mt][2] = *(const u32*)(Z + r * ZS + kcol + 8);
                    A[mt][3] = *(const u32*)(Z + (r + 8) * ZS + kcol + 8);
                }
#pragma unroll
                for (int nt = 0; nt < 4; nt++) {
                    int n = n_idx * 32 + nt * 8 + g;
                    u32 B0 = *(const u32*)(Wp + n * 72 + ks * 16 + tig * 2);
                    u32 B1 = *(const u32*)(Wp + n * 72 + ks * 16 + tig * 2 + 8);
                    mma16(acc[0][nt], A[0], B0, B1);
                    mma16(acc[1][nt], A[1], B0, B1);
                }
            }
            __syncthreads();  // buffer reuse guard (next pc / next pass)
        }

        if (pass == 0) {
            // z2 = relu(acc + b1) -> Z tile; then preload lin2 chunks
#pragma unroll
            for (int mt = 0; mt < 2; mt++) {
#pragma unroll
                for (int nt = 0; nt < 4; nt++) {
                    int o0 = n_idx * 32 + nt * 8 + tig * 2;
                    int r0 = m_idx * 32 + mt * 16 + g;
                    float b0 = B1S[o0], b1 = B1S[o0 + 1];
                    *(__half2*)(Z + r0 * ZS + o0) = __floats2half2_rn(
                        fmaxf(acc[mt][nt][0] + b0, 0.f), fmaxf(acc[mt][nt][1] + b1, 0.f));
                    *(__half2*)(Z + (r0 + 8) * ZS + o0) = __floats2half2_rn(
                        fmaxf(acc[mt][nt][2] + b0, 0.f), fmaxf(acc[mt][nt][3] + b1, 0.f));
                }
            }
            __syncthreads();
#pragma unroll
            for (int pc = 0; pc < 2; pc++) {
                u32 d = smb + FWB_B + pc * 18432;
                const char* s = (const char*)(g_lin_h) + 36864 + pc * 18432;
#pragma unroll
                for (int j = 0; j < 5; j++) {
                    int e = tid + j * 256;
                    if (e < 1152) cpa16(d + e * 16, s + e * 16);
                }
                CP_COMMIT();
            }
        } else {
            // out layout [T][B][C]
#pragma unroll
            for (int mt = 0; mt < 2; mt++) {
#pragma unroll
                for (int nt = 0; nt < 4; nt++) {
                    int o0 = n_idx * 32 + nt * 8 + tig * 2;
                    int r0 = m_idx * 32 + mt * 16 + g;
                    float b0 = B2S[o0], b1 = B2S[o0 + 1];
                    float2 v0, v1;
                    v0.x = acc[mt][nt][0] + b0;
                    v0.y = acc[mt][nt][1] + b1;
                    v1.x = acc[mt][nt][2] + b0;
                    v1.y = acc[mt][nt][3] + b1;
                    *(float2*)(out + ((size_t)(t0 + r0) * NB + b) * NC + o0) = v0;
                    *(float2*)(out + ((size_t)(t0 + r0 + 8) * NB + b) * NC + o0) = v1;
                }
            }
        }
    }
}

// ---------------- launch -----------------------------------------------------

extern "C" void kernel_launch(void* const* d_in, const int* in_sizes, int n_in,
                              void* d_out, int out_size) {
    const float* x      = (const float*)d_in[0];
    const float* pre_w  = (const float*)d_in[1];
    const float* pre_b  = (const float*)d_in[2];
    const float* conv_w = (const float*)d_in[3];
    const float* conv_b = (const float*)d_in[4];
    const float* post_w = (const float*)d_in[5];
    const float* post_b = (const float*)d_in[6];
    const float* lin1_w = (const float*)d_in[7];
    const float* lin1_b = (const float*)d_in[8];
    const float* lin2_w = (const float*)d_in[9];
    const float* lin2_b = (const float*)d_in[10];

    cudaFuncSetAttribute(layer_kernel, cudaFuncAttributeMaxDynamicSharedMemorySize, SMEM_LAYER);
    cudaFuncSetAttribute(final_kernel, cudaFuncAttributeMaxDynamicSharedMemorySize, SMEM_FINAL);

    tconv_kernel<<<10240, 256>>>(conv_w);
    tpost_kernel<<<2560, 256>>>(post_w);
    tlin_kernel<<<64, 256>>>(lin1_w, 0);
    tlin_kernel<<<64, 256>>>(lin2_w, 1);

    pre_kernel<<<NB * NT, 128>>>(x, pre_w, pre_b);

    for (int i = 0; i < NL; ++i) {
        int d = 1 << (i % 10);
        layer_kernel<<<512, 256, SMEM_LAYER>>>(i, d, i & 1, (i == 0) ? 1 : 0,
                                               conv_b, post_b);
    }

    final_kernel<<<512, 256, SMEM_FINAL>>>(lin1_b, lin2_b, (float*)d_out);
}